// round 1
// baseline (speedup 1.0000x reference)
#include <cuda_runtime.h>
#include <cuda_bf16.h>
#include <math.h>

// ---------------------------------------------------------------------------
// Problem constants
// ---------------------------------------------------------------------------
#define T_SEQ    3072
#define DIM      2048
#define N_HEADS  16
#define Q_LORA   1536
#define KV_LORA  512
#define NOPE     128
#define ROPE     64
#define V_DIM    128
#define HD       (NOPE + ROPE)       // 192
#define EPS      1e-6f

// ---------------------------------------------------------------------------
// Scratch (static device globals -- no allocations allowed)
// ---------------------------------------------------------------------------
__device__ float g_qdt  [T_SEQ * Q_LORA];          // x @ wq_down (pre-norm)
__device__ float g_qlat [T_SEQ * Q_LORA];          // rmsnorm'd q latent
__device__ float g_qnope[T_SEQ * N_HEADS * NOPE];  // q_lat @ wq_nope
__device__ float g_qrope[T_SEQ * N_HEADS * ROPE];  // q_lat @ wq_rope (pre-rope)
__device__ float g_kvd  [T_SEQ * (KV_LORA + ROPE)];// x @ wkv_down
__device__ float g_ckvn [T_SEQ * KV_LORA];         // rmsnorm'd kv latent
__device__ float g_kvup [T_SEQ * N_HEADS * (NOPE + V_DIM)]; // kv up-proj (k_nope | v)
__device__ float g_q    [T_SEQ * N_HEADS * HD];    // assembled Q  [t][h][192]
__device__ float g_k    [T_SEQ * N_HEADS * HD];    // assembled K  [t][h][192]
__device__ float g_o    [T_SEQ * N_HEADS * V_DIM]; // attention out [t][h*128]

// ---------------------------------------------------------------------------
// SGEMM: C[M,N] = A[M,K] @ B[K,N], row-major fp32.
// 128x128 block, BK=16, 256 threads, 8x8 register microtile.
// Requirements: M % 128 == 0, K % 16 == 0, N % 4 == 0 (col guard for N%128!=0).
// ---------------------------------------------------------------------------
__global__ __launch_bounds__(256)
void sgemm128(const float* __restrict__ A, const float* __restrict__ B,
              float* __restrict__ C, int M, int N, int K) {
    __shared__ float As[16][132];   // transposed A tile (padded)
    __shared__ float Bs[16][128];

    const int tid = threadIdx.x;
    const int bm  = blockIdx.y, bn = blockIdx.x;
    const int tx  = tid & 15, ty = tid >> 4;
    const int rowA0 = bm * 128;
    const int colB0 = bn * 128;

    float acc[8][8];
    #pragma unroll
    for (int i = 0; i < 8; i++)
        #pragma unroll
        for (int j = 0; j < 8; j++) acc[i][j] = 0.f;

    for (int k0 = 0; k0 < K; k0 += 16) {
        // load A tile: 128 rows x 16 cols, transposed into As
        #pragma unroll
        for (int l = 0; l < 2; l++) {
            int idx = tid + l * 256;
            int r = idx >> 2, c4 = idx & 3;
            float4 v = *(const float4*)&A[(size_t)(rowA0 + r) * K + k0 + c4 * 4];
            As[c4 * 4 + 0][r] = v.x;
            As[c4 * 4 + 1][r] = v.y;
            As[c4 * 4 + 2][r] = v.z;
            As[c4 * 4 + 3][r] = v.w;
        }
        // load B tile: 16 rows x 128 cols
        #pragma unroll
        for (int l = 0; l < 2; l++) {
            int idx = tid + l * 256;
            int kr = idx >> 5, c4 = idx & 31;
            int col = colB0 + c4 * 4;
            float4 v = make_float4(0.f, 0.f, 0.f, 0.f);
            if (col < N) v = *(const float4*)&B[(size_t)(k0 + kr) * N + col];
            *(float4*)&Bs[kr][c4 * 4] = v;
        }
        __syncthreads();

        #pragma unroll
        for (int kk = 0; kk < 16; kk++) {
            float af[8], bf[8];
            *(float4*)&af[0] = *(float4*)&As[kk][ty * 8];
            *(float4*)&af[4] = *(float4*)&As[kk][ty * 8 + 4];
            *(float4*)&bf[0] = *(float4*)&Bs[kk][tx * 8];
            *(float4*)&bf[4] = *(float4*)&Bs[kk][tx * 8 + 4];
            #pragma unroll
            for (int i = 0; i < 8; i++)
                #pragma unroll
                for (int j = 0; j < 8; j++)
                    acc[i][j] += af[i] * bf[j];
        }
        __syncthreads();
    }

    #pragma unroll
    for (int i = 0; i < 8; i++) {
        int row = rowA0 + ty * 8 + i;
        #pragma unroll
        for (int j4 = 0; j4 < 2; j4++) {
            int col = colB0 + tx * 8 + j4 * 4;
            if (col < N)
                *(float4*)&C[(size_t)row * N + col] = *(float4*)&acc[i][j4 * 4];
        }
    }
}

// ---------------------------------------------------------------------------
// Row-wise RMSNorm: one block per row
// ---------------------------------------------------------------------------
__global__ __launch_bounds__(256)
void rmsnorm_kernel(const float* __restrict__ in, const float* __restrict__ w,
                    float* __restrict__ out, int instride, int outstride, int cols) {
    int r = blockIdx.x;
    const float* row = in + (size_t)r * instride;
    float ss = 0.f;
    for (int c = threadIdx.x; c < cols; c += blockDim.x) {
        float v = row[c];
        ss += v * v;
    }
    __shared__ float red[8];
    int lane = threadIdx.x & 31, wid = threadIdx.x >> 5;
    #pragma unroll
    for (int o = 16; o; o >>= 1) ss += __shfl_xor_sync(0xFFFFFFFFu, ss, o);
    if (lane == 0) red[wid] = ss;
    __syncthreads();
    if (wid == 0) {
        float v = (lane < 8) ? red[lane] : 0.f;
        #pragma unroll
        for (int o = 4; o; o >>= 1) v += __shfl_xor_sync(0xFFFFFFFFu, v, o);
        if (lane == 0) red[0] = v;
    }
    __syncthreads();
    float inv = rsqrtf(red[0] / (float)cols + EPS);
    float* orow = out + (size_t)r * outstride;
    for (int c = threadIdx.x; c < cols; c += blockDim.x)
        orow[c] = row[c] * inv * w[c];
}

// ---------------------------------------------------------------------------
// Assemble Q: copy nope part + apply RoPE to rope part.  one block per t.
// ---------------------------------------------------------------------------
__global__ __launch_bounds__(256)
void assemble_q(const float* __restrict__ freqs) {
    int t = blockIdx.x;
    int tid = threadIdx.x;
    // nope copy: 16 heads * 128 = 2048 floats = 512 float4
    for (int i = tid; i < 512; i += 256) {
        int e = i * 4;
        int h = e >> 7, d = e & 127;
        *(float4*)&g_q[(size_t)t * (N_HEADS * HD) + h * HD + d] =
            *(const float4*)&g_qnope[(size_t)t * (N_HEADS * NOPE) + e];
    }
    // rope: 16 heads * 32 pairs
    for (int i = tid; i < N_HEADS * 32; i += 256) {
        int h = i >> 5, p = i & 31;
        float f = freqs[t * 32 + p];
        float c = cosf(f), s = sinf(f);
        const float* src = &g_qrope[(size_t)t * (N_HEADS * ROPE) + h * ROPE + 2 * p];
        float x1 = src[0], x2 = src[1];
        float* dst = &g_q[(size_t)t * (N_HEADS * HD) + h * HD + NOPE + 2 * p];
        dst[0] = x1 * c - x2 * s;
        dst[1] = x1 * s + x2 * c;
    }
}

// ---------------------------------------------------------------------------
// Assemble K: k_nope from kv_up + broadcast RoPE'd k_rope from kvd.
// ---------------------------------------------------------------------------
__global__ __launch_bounds__(256)
void assemble_k(const float* __restrict__ freqs) {
    int t = blockIdx.x;
    int tid = threadIdx.x;
    // nope: per head 128 from kvup[t][h*256 + d]
    for (int i = tid; i < 512; i += 256) {
        int e = i * 4;
        int h = e >> 7, d = e & 127;
        *(float4*)&g_k[(size_t)t * (N_HEADS * HD) + h * HD + d] =
            *(const float4*)&g_kvup[(size_t)t * (N_HEADS * (NOPE + V_DIM)) + h * (NOPE + V_DIM) + d];
    }
    __shared__ float rk[ROPE];
    if (tid < 32) {
        float f = freqs[t * 32 + tid];
        float c = cosf(f), s = sinf(f);
        const float* src = &g_kvd[(size_t)t * (KV_LORA + ROPE) + KV_LORA + 2 * tid];
        float x1 = src[0], x2 = src[1];
        rk[2 * tid]     = x1 * c - x2 * s;
        rk[2 * tid + 1] = x1 * s + x2 * c;
    }
    __syncthreads();
    for (int i = tid; i < N_HEADS * ROPE; i += 256) {
        int h = i >> 6, d = i & 63;
        g_k[(size_t)t * (N_HEADS * HD) + h * HD + NOPE + d] = rk[d];
    }
}

// ---------------------------------------------------------------------------
// Causal flash attention.
// Grid: (T/64 q-tiles, 16 heads). Block: 256 threads = 8 warps.
// Warp w owns 8 queries; lane = key within a 32-key tile.
// Dynamic smem: Qs[64][196] | Ks[32][196] | Vs[32][128] | Ps[64][32]
// ---------------------------------------------------------------------------
#define Q_STRIDE 196
#define SMEM_ATTN ((64 * Q_STRIDE + 32 * Q_STRIDE + 32 * 128 + 64 * 32) * 4)

__global__ __launch_bounds__(256)
void attn_kernel() {
    extern __shared__ float sm[];
    float* Qs = sm;                         // [64][196]
    float* Ks = Qs + 64 * Q_STRIDE;         // [32][196]
    float* Vs = Ks + 32 * Q_STRIDE;         // [32][128]
    float* Ps = Vs + 32 * 128;              // [64][32]

    const int h   = blockIdx.y;
    const int qt  = blockIdx.x;
    const int tid = threadIdx.x;
    const int w   = tid >> 5, lane = tid & 31;
    const int q0  = qt * 64;
    const float scale = 0.07216878364870323f;   // 1/sqrt(192)

    // load Q tile: 64 x 192 floats
    for (int i = tid; i < 64 * 48; i += 256) {
        int r = i / 48, c4 = i % 48;
        *(float4*)&Qs[r * Q_STRIDE + c4 * 4] =
            *(const float4*)&g_q[(size_t)(q0 + r) * (N_HEADS * HD) + h * HD + c4 * 4];
    }

    float m[8], l[8], acc[8][4];
    #pragma unroll
    for (int q = 0; q < 8; q++) {
        m[q] = -1e30f; l[q] = 0.f;
        acc[q][0] = acc[q][1] = acc[q][2] = acc[q][3] = 0.f;
    }
    const int qbase  = q0 + w * 8;
    const int ntiles = 2 * qt + 2;

    for (int kt = 0; kt < ntiles; kt++) {
        __syncthreads();
        // load K tile 32x192
        for (int i = tid; i < 32 * 48; i += 256) {
            int r = i / 48, c4 = i % 48;
            *(float4*)&Ks[r * Q_STRIDE + c4 * 4] =
                *(const float4*)&g_k[(size_t)(kt * 32 + r) * (N_HEADS * HD) + h * HD + c4 * 4];
        }
        // load V tile 32x128
        for (int i = tid; i < 32 * 32; i += 256) {
            int r = i >> 5, c4 = i & 31;
            *(float4*)&Vs[r * 128 + c4 * 4] =
                *(const float4*)&g_kvup[(size_t)(kt * 32 + r) * (N_HEADS * (NOPE + V_DIM))
                                        + h * (NOPE + V_DIM) + NOPE + c4 * 4];
        }
        __syncthreads();

        // scores: lane's key
        float s[8];
        #pragma unroll
        for (int q = 0; q < 8; q++) s[q] = 0.f;
        #pragma unroll 4
        for (int d4 = 0; d4 < 48; d4++) {
            float4 kv = *(float4*)&Ks[lane * Q_STRIDE + d4 * 4];
            #pragma unroll
            for (int q = 0; q < 8; q++) {
                float4 qv = *(float4*)&Qs[(w * 8 + q) * Q_STRIDE + d4 * 4];
                s[q] += qv.x * kv.x + qv.y * kv.y + qv.z * kv.z + qv.w * kv.w;
            }
        }

        const int jg = kt * 32 + lane;
        #pragma unroll
        for (int q = 0; q < 8; q++) {
            int qg = qbase + q;
            float sv = (jg <= qg) ? s[q] * scale : -1e30f;
            float tm = sv;
            #pragma unroll
            for (int o = 16; o; o >>= 1) tm = fmaxf(tm, __shfl_xor_sync(0xFFFFFFFFu, tm, o));
            float nm = fmaxf(m[q], tm);
            float sc = __expf(m[q] - nm);
            float p  = __expf(sv - nm);
            m[q] = nm;
            float ps = p;
            #pragma unroll
            for (int o = 16; o; o >>= 1) ps += __shfl_xor_sync(0xFFFFFFFFu, ps, o);
            l[q] = l[q] * sc + ps;
            acc[q][0] *= sc; acc[q][1] *= sc; acc[q][2] *= sc; acc[q][3] *= sc;
            Ps[(w * 8 + q) * 32 + lane] = p;
        }
        __syncwarp();

        // accumulate P @ V  (lane owns dims [lane*4, lane*4+4))
        #pragma unroll 8
        for (int j = 0; j < 32; j++) {
            float4 v4 = *(float4*)&Vs[j * 128 + lane * 4];
            #pragma unroll
            for (int q = 0; q < 8; q++) {
                float p = Ps[(w * 8 + q) * 32 + j];
                acc[q][0] += p * v4.x;
                acc[q][1] += p * v4.y;
                acc[q][2] += p * v4.z;
                acc[q][3] += p * v4.w;
            }
        }
    }

    #pragma unroll
    for (int q = 0; q < 8; q++) {
        float inv = 1.f / l[q];
        int qg = qbase + q;
        float4 o4 = make_float4(acc[q][0] * inv, acc[q][1] * inv,
                                acc[q][2] * inv, acc[q][3] * inv);
        *(float4*)&g_o[(size_t)qg * (N_HEADS * V_DIM) + h * V_DIM + lane * 4] = o4;
    }
}

// ---------------------------------------------------------------------------
// Launcher
// ---------------------------------------------------------------------------
extern "C" void kernel_launch(void* const* d_in, const int* in_sizes, int n_in,
                              void* d_out, int out_size) {
    const float* x         = (const float*)d_in[0];
    const float* freqs     = (const float*)d_in[1];
    // d_in[2] = mask (causal, rebuilt implicitly)
    const float* wq_down   = (const float*)d_in[3];
    const float* q_norm_w  = (const float*)d_in[4];
    const float* wq_nope   = (const float*)d_in[5];
    const float* wq_rope   = (const float*)d_in[6];
    const float* wkv_down  = (const float*)d_in[7];
    const float* kv_norm_w = (const float*)d_in[8];
    const float* wkv_up    = (const float*)d_in[9];
    const float* wo        = (const float*)d_in[10];
    float* out = (float*)d_out;

    // resolve device-global scratch addresses (idempotent, capture-safe)
    float *p_qdt, *p_qlat, *p_qnope, *p_qrope, *p_kvd, *p_ckvn, *p_kvup, *p_o;
    cudaGetSymbolAddress((void**)&p_qdt,   g_qdt);
    cudaGetSymbolAddress((void**)&p_qlat,  g_qlat);
    cudaGetSymbolAddress((void**)&p_qnope, g_qnope);
    cudaGetSymbolAddress((void**)&p_qrope, g_qrope);
    cudaGetSymbolAddress((void**)&p_kvd,   g_kvd);
    cudaGetSymbolAddress((void**)&p_ckvn,  g_ckvn);
    cudaGetSymbolAddress((void**)&p_kvup,  g_kvup);
    cudaGetSymbolAddress((void**)&p_o,     g_o);

    const dim3 blk(256);
    const int MB = T_SEQ / 128;   // 24 block-rows

    // 1) q down-proj
    sgemm128<<<dim3(Q_LORA / 128, MB), blk>>>(x, wq_down, p_qdt, T_SEQ, Q_LORA, DIM);
    // 2) rmsnorm -> q latent
    rmsnorm_kernel<<<T_SEQ, 256>>>(p_qdt, q_norm_w, p_qlat, Q_LORA, Q_LORA, Q_LORA);
    // 3) q nope / rope up-proj
    sgemm128<<<dim3((N_HEADS * NOPE) / 128, MB), blk>>>(p_qlat, wq_nope, p_qnope, T_SEQ, N_HEADS * NOPE, Q_LORA);
    sgemm128<<<dim3((N_HEADS * ROPE) / 128, MB), blk>>>(p_qlat, wq_rope, p_qrope, T_SEQ, N_HEADS * ROPE, Q_LORA);
    // 4) kv down-proj (N=576 -> 5 col-blocks, guarded)
    sgemm128<<<dim3((KV_LORA + ROPE + 127) / 128, MB), blk>>>(x, wkv_down, p_kvd, T_SEQ, KV_LORA + ROPE, DIM);
    // 5) rmsnorm kv latent
    rmsnorm_kernel<<<T_SEQ, 256>>>(p_kvd, kv_norm_w, p_ckvn, KV_LORA + ROPE, KV_LORA, KV_LORA);
    // 6) kv up-proj
    sgemm128<<<dim3((N_HEADS * (NOPE + V_DIM)) / 128, MB), blk>>>(p_ckvn, wkv_up, p_kvup, T_SEQ, N_HEADS * (NOPE + V_DIM), KV_LORA);
    // 7) assemble Q (rope) and K (rope + broadcast)
    assemble_q<<<T_SEQ, 256>>>(freqs);
    assemble_k<<<T_SEQ, 256>>>(freqs);
    // 8) causal attention
    cudaFuncSetAttribute(attn_kernel, cudaFuncAttributeMaxDynamicSharedMemorySize, SMEM_ATTN);
    attn_kernel<<<dim3(T_SEQ / 64, N_HEADS), 256, SMEM_ATTN>>>();
    // 9) output projection
    sgemm128<<<dim3(DIM / 128, MB), blk>>>(p_o, wo, out, T_SEQ, DIM, DIM);
}

// round 3
// speedup vs baseline: 1.4711x; 1.4711x over previous
#include <cuda_runtime.h>
#include <cuda_bf16.h>
#include <cstdint>
#include <math.h>

// ---------------------------------------------------------------------------
// Problem constants
// ---------------------------------------------------------------------------
#define T_SEQ    3072
#define DIM      2048
#define N_HEADS  16
#define Q_LORA   1536
#define KV_LORA  512
#define NOPE     128
#define ROPE     64
#define V_DIM    128
#define HD       (NOPE + ROPE)       // 192
#define EPS      1e-6f
#define KVD_PAD  640                 // kv_down N=576 padded to 640

__device__ __forceinline__ float to_tf32(float x) {
    uint32_t u; asm("cvt.rna.tf32.f32 %0, %1;" : "=r"(u) : "f"(x));
    return __uint_as_float(u);
}

// ---------------------------------------------------------------------------
// Scratch (static device globals -- no allocations allowed)
// ---------------------------------------------------------------------------
__device__ float g_qdt  [T_SEQ * Q_LORA];
__device__ float g_qlat [T_SEQ * Q_LORA];
__device__ float g_qnope[T_SEQ * N_HEADS * NOPE];
__device__ float g_qrope[T_SEQ * N_HEADS * ROPE];
__device__ float g_kvd  [T_SEQ * KVD_PAD];            // padded stride 640
__device__ float g_ckvn [T_SEQ * KV_LORA];
__device__ float g_kvup [T_SEQ * N_HEADS * (NOPE + V_DIM)];
__device__ float g_q    [T_SEQ * N_HEADS * HD];
__device__ float g_k    [T_SEQ * N_HEADS * HD];
__device__ float g_o    [T_SEQ * N_HEADS * V_DIM];

// transposed (K-major [N][K]) tf32-rounded weights
__device__ float g_wqdT [Q_LORA * DIM];
__device__ float g_wqnT [(N_HEADS * NOPE) * Q_LORA];
__device__ float g_wqrT [(N_HEADS * ROPE) * Q_LORA];
__device__ float g_wkdT [KVD_PAD * DIM];
__device__ float g_wkuT [(N_HEADS * (NOPE + V_DIM)) * KV_LORA];
__device__ float g_woT  [DIM * (N_HEADS * V_DIM)];

// ---------------------------------------------------------------------------
// Weight transpose: src[K][N] row-major -> dst[NP][K] (tf32-rounded, zero pad)
// ---------------------------------------------------------------------------
__global__ __launch_bounds__(256)
void transpose_tf32(const float* __restrict__ src, float* __restrict__ dst,
                    int K, int N, int NP) {
    __shared__ float tile[32][33];
    int kb = blockIdx.y * 32, nb = blockIdx.x * 32;
    for (int i = threadIdx.y; i < 32; i += 8) {
        int n = nb + threadIdx.x;
        float v = (n < N) ? src[(size_t)(kb + i) * N + n] : 0.f;
        tile[i][threadIdx.x] = v;
    }
    __syncthreads();
    for (int i = threadIdx.y; i < 32; i += 8) {
        int n = nb + i;
        if (n < NP)
            dst[(size_t)n * K + kb + threadIdx.x] = to_tf32(tile[threadIdx.x][i]);
    }
}

// ---------------------------------------------------------------------------
// TF32 mma.sync GEMM: C[M,N] = A[M,K] @ Bt[N,K]^T
// CTA 128x128, BK=16, 8 warps (2x4), warp tile 64x32.
// A: row-major fp32 (tf32-rounded on smem store). Bt: [N][K] tf32.
// Requires M%128==0, N%128==0, K%16==0.
// ---------------------------------------------------------------------------
#define SMS 20   // smem row stride in floats (16 data + 4 pad)

__global__ __launch_bounds__(256)
void mma_gemm(const float* __restrict__ A, const float* __restrict__ Bt,
              float* __restrict__ C, int M, int N, int K) {
    __shared__ float As[2][128 * SMS];
    __shared__ float Bs[2][128 * SMS];

    const int tid  = threadIdx.x;
    const int wid  = tid >> 5, lane = tid & 31;
    const int gid  = lane >> 2, tig = lane & 3;       // group / thread-in-group
    const int wm   = wid >> 2, wn = wid & 3;          // warp tile coords
    const int bm   = blockIdx.y, bn = blockIdx.x;

    const float* Ab = A  + (size_t)bm * 128 * K;
    const float* Bb = Bt + (size_t)bn * 128 * K;

    const int r  = tid >> 2;        // 0..63? no: tid>>2 over 256 → 0..63. Need 128 rows via 2 iters
    const int c4 = tid & 3;

    float acc[4][4][4];
    #pragma unroll
    for (int i = 0; i < 4; i++)
        #pragma unroll
        for (int j = 0; j < 4; j++)
            #pragma unroll
            for (int k = 0; k < 4; k++) acc[i][j][k] = 0.f;

    const int nk = K >> 4;

    // preload tile 0
    {
        #pragma unroll
        for (int l = 0; l < 2; l++) {
            int row = r + l * 64;
            float4 va = *(const float4*)&Ab[(size_t)row * K + c4 * 4];
            va.x = to_tf32(va.x); va.y = to_tf32(va.y);
            va.z = to_tf32(va.z); va.w = to_tf32(va.w);
            *(float4*)&As[0][row * SMS + c4 * 4] = va;
            float4 vb = *(const float4*)&Bb[(size_t)row * K + c4 * 4];
            *(float4*)&Bs[0][row * SMS + c4 * 4] = vb;
        }
    }
    __syncthreads();

    for (int kt = 0; kt < nk; kt++) {
        const int cur = kt & 1;

        // prefetch next tile into registers
        float4 pa[2], pb[2];
        if (kt + 1 < nk) {
            const int k0 = (kt + 1) * 16;
            #pragma unroll
            for (int l = 0; l < 2; l++) {
                int row = r + l * 64;
                pa[l] = *(const float4*)&Ab[(size_t)row * K + k0 + c4 * 4];
                pb[l] = *(const float4*)&Bb[(size_t)row * K + k0 + c4 * 4];
            }
        }

        // compute on current tile
        const float* as = As[cur];
        const float* bs = Bs[cur];
        #pragma unroll
        for (int ks = 0; ks < 2; ks++) {
            uint32_t a[4][4], b[4][2];
            #pragma unroll
            for (int mf = 0; mf < 4; mf++) {
                int row = wm * 64 + mf * 16 + gid;
                int kk  = ks * 8 + tig;
                a[mf][0] = __float_as_uint(as[row * SMS + kk]);
                a[mf][1] = __float_as_uint(as[(row + 8) * SMS + kk]);
                a[mf][2] = __float_as_uint(as[row * SMS + kk + 4]);
                a[mf][3] = __float_as_uint(as[(row + 8) * SMS + kk + 4]);
            }
            #pragma unroll
            for (int nf = 0; nf < 4; nf++) {
                int col = wn * 32 + nf * 8 + gid;
                int kk  = ks * 8 + tig;
                b[nf][0] = __float_as_uint(bs[col * SMS + kk]);
                b[nf][1] = __float_as_uint(bs[col * SMS + kk + 4]);
            }
            #pragma unroll
            for (int mf = 0; mf < 4; mf++)
                #pragma unroll
                for (int nf = 0; nf < 4; nf++) {
                    asm volatile(
                        "mma.sync.aligned.m16n8k8.row.col.f32.tf32.tf32.f32 "
                        "{%0,%1,%2,%3}, {%4,%5,%6,%7}, {%8,%9}, {%0,%1,%2,%3};"
                        : "+f"(acc[mf][nf][0]), "+f"(acc[mf][nf][1]),
                          "+f"(acc[mf][nf][2]), "+f"(acc[mf][nf][3])
                        : "r"(a[mf][0]), "r"(a[mf][1]), "r"(a[mf][2]), "r"(a[mf][3]),
                          "r"(b[nf][0]), "r"(b[nf][1]));
                }
        }

        // store prefetched tile into the other buffer
        if (kt + 1 < nk) {
            const int nxt = cur ^ 1;
            #pragma unroll
            for (int l = 0; l < 2; l++) {
                int row = r + l * 64;
                float4 va = pa[l];
                va.x = to_tf32(va.x); va.y = to_tf32(va.y);
                va.z = to_tf32(va.z); va.w = to_tf32(va.w);
                *(float4*)&As[nxt][row * SMS + c4 * 4] = va;
                *(float4*)&Bs[nxt][row * SMS + c4 * 4] = pb[l];
            }
        }
        __syncthreads();
    }

    // epilogue
    #pragma unroll
    for (int mf = 0; mf < 4; mf++) {
        int row0 = bm * 128 + wm * 64 + mf * 16 + gid;
        #pragma unroll
        for (int nf = 0; nf < 4; nf++) {
            int col = bn * 128 + wn * 32 + nf * 8 + tig * 2;
            *(float2*)&C[(size_t)row0 * N + col]       = make_float2(acc[mf][nf][0], acc[mf][nf][1]);
            *(float2*)&C[(size_t)(row0 + 8) * N + col] = make_float2(acc[mf][nf][2], acc[mf][nf][3]);
        }
    }
}

// ---------------------------------------------------------------------------
// Row-wise RMSNorm
// ---------------------------------------------------------------------------
__global__ __launch_bounds__(256)
void rmsnorm_kernel(const float* __restrict__ in, const float* __restrict__ w,
                    float* __restrict__ out, int instride, int outstride, int cols) {
    int r = blockIdx.x;
    const float* row = in + (size_t)r * instride;
    float ss = 0.f;
    for (int c = threadIdx.x; c < cols; c += blockDim.x) {
        float v = row[c];
        ss += v * v;
    }
    __shared__ float red[8];
    int lane = threadIdx.x & 31, wid = threadIdx.x >> 5;
    #pragma unroll
    for (int o = 16; o; o >>= 1) ss += __shfl_xor_sync(0xFFFFFFFFu, ss, o);
    if (lane == 0) red[wid] = ss;
    __syncthreads();
    if (wid == 0) {
        float v = (lane < 8) ? red[lane] : 0.f;
        #pragma unroll
        for (int o = 4; o; o >>= 1) v += __shfl_xor_sync(0xFFFFFFFFu, v, o);
        if (lane == 0) red[0] = v;
    }
    __syncthreads();
    float inv = rsqrtf(red[0] / (float)cols + EPS);
    float* orow = out + (size_t)r * outstride;
    for (int c = threadIdx.x; c < cols; c += blockDim.x)
        orow[c] = row[c] * inv * w[c];
}

// ---------------------------------------------------------------------------
// Assemble Q
// ---------------------------------------------------------------------------
__global__ __launch_bounds__(256)
void assemble_q(const float* __restrict__ freqs) {
    int t = blockIdx.x;
    int tid = threadIdx.x;
    for (int i = tid; i < 512; i += 256) {
        int e = i * 4;
        int h = e >> 7, d = e & 127;
        *(float4*)&g_q[(size_t)t * (N_HEADS * HD) + h * HD + d] =
            *(const float4*)&g_qnope[(size_t)t * (N_HEADS * NOPE) + e];
    }
    for (int i = tid; i < N_HEADS * 32; i += 256) {
        int h = i >> 5, p = i & 31;
        float f = freqs[t * 32 + p];
        float c = cosf(f), s = sinf(f);
        const float* src = &g_qrope[(size_t)t * (N_HEADS * ROPE) + h * ROPE + 2 * p];
        float x1 = src[0], x2 = src[1];
        float* dst = &g_q[(size_t)t * (N_HEADS * HD) + h * HD + NOPE + 2 * p];
        dst[0] = x1 * c - x2 * s;
        dst[1] = x1 * s + x2 * c;
    }
}

// ---------------------------------------------------------------------------
// Assemble K
// ---------------------------------------------------------------------------
__global__ __launch_bounds__(256)
void assemble_k(const float* __restrict__ freqs) {
    int t = blockIdx.x;
    int tid = threadIdx.x;
    for (int i = tid; i < 512; i += 256) {
        int e = i * 4;
        int h = e >> 7, d = e & 127;
        *(float4*)&g_k[(size_t)t * (N_HEADS * HD) + h * HD + d] =
            *(const float4*)&g_kvup[(size_t)t * (N_HEADS * (NOPE + V_DIM)) + h * (NOPE + V_DIM) + d];
    }
    __shared__ float rk[ROPE];
    if (tid < 32) {
        float f = freqs[t * 32 + tid];
        float c = cosf(f), s = sinf(f);
        const float* src = &g_kvd[(size_t)t * KVD_PAD + KV_LORA + 2 * tid];
        float x1 = src[0], x2 = src[1];
        rk[2 * tid]     = x1 * c - x2 * s;
        rk[2 * tid + 1] = x1 * s + x2 * c;
    }
    __syncthreads();
    for (int i = tid; i < N_HEADS * ROPE; i += 256) {
        int h = i >> 6, d = i & 63;
        g_k[(size_t)t * (N_HEADS * HD) + h * HD + NOPE + d] = rk[d];
    }
}

// ---------------------------------------------------------------------------
// Causal flash attention (SIMT fp32, unchanged from R1)
// ---------------------------------------------------------------------------
#define Q_STRIDE 196
#define SMEM_ATTN ((64 * Q_STRIDE + 32 * Q_STRIDE + 32 * 128 + 64 * 32) * 4)

__global__ __launch_bounds__(256)
void attn_kernel() {
    extern __shared__ float sm[];
    float* Qs = sm;
    float* Ks = Qs + 64 * Q_STRIDE;
    float* Vs = Ks + 32 * Q_STRIDE;
    float* Ps = Vs + 32 * 128;

    const int h   = blockIdx.y;
    const int qt  = blockIdx.x;
    const int tid = threadIdx.x;
    const int w   = tid >> 5, lane = tid & 31;
    const int q0  = qt * 64;
    const float scale = 0.07216878364870323f;

    for (int i = tid; i < 64 * 48; i += 256) {
        int r = i / 48, c4 = i % 48;
        *(float4*)&Qs[r * Q_STRIDE + c4 * 4] =
            *(const float4*)&g_q[(size_t)(q0 + r) * (N_HEADS * HD) + h * HD + c4 * 4];
    }

    float m[8], l[8], acc[8][4];
    #pragma unroll
    for (int q = 0; q < 8; q++) {
        m[q] = -1e30f; l[q] = 0.f;
        acc[q][0] = acc[q][1] = acc[q][2] = acc[q][3] = 0.f;
    }
    const int qbase  = q0 + w * 8;
    const int ntiles = 2 * qt + 2;

    for (int kt = 0; kt < ntiles; kt++) {
        __syncthreads();
        for (int i = tid; i < 32 * 48; i += 256) {
            int r = i / 48, c4 = i % 48;
            *(float4*)&Ks[r * Q_STRIDE + c4 * 4] =
                *(const float4*)&g_k[(size_t)(kt * 32 + r) * (N_HEADS * HD) + h * HD + c4 * 4];
        }
        for (int i = tid; i < 32 * 32; i += 256) {
            int r = i >> 5, c4 = i & 31;
            *(float4*)&Vs[r * 128 + c4 * 4] =
                *(const float4*)&g_kvup[(size_t)(kt * 32 + r) * (N_HEADS * (NOPE + V_DIM))
                                        + h * (NOPE + V_DIM) + NOPE + c4 * 4];
        }
        __syncthreads();

        float s[8];
        #pragma unroll
        for (int q = 0; q < 8; q++) s[q] = 0.f;
        #pragma unroll 4
        for (int d4 = 0; d4 < 48; d4++) {
            float4 kv = *(float4*)&Ks[lane * Q_STRIDE + d4 * 4];
            #pragma unroll
            for (int q = 0; q < 8; q++) {
                float4 qv = *(float4*)&Qs[(w * 8 + q) * Q_STRIDE + d4 * 4];
                s[q] += qv.x * kv.x + qv.y * kv.y + qv.z * kv.z + qv.w * kv.w;
            }
        }

        const int jg = kt * 32 + lane;
        #pragma unroll
        for (int q = 0; q < 8; q++) {
            int qg = qbase + q;
            float sv = (jg <= qg) ? s[q] * scale : -1e30f;
            float tm = sv;
            #pragma unroll
            for (int o = 16; o; o >>= 1) tm = fmaxf(tm, __shfl_xor_sync(0xFFFFFFFFu, tm, o));
            float nm = fmaxf(m[q], tm);
            float sc = __expf(m[q] - nm);
            float p  = __expf(sv - nm);
            m[q] = nm;
            float ps = p;
            #pragma unroll
            for (int o = 16; o; o >>= 1) ps += __shfl_xor_sync(0xFFFFFFFFu, ps, o);
            l[q] = l[q] * sc + ps;
            acc[q][0] *= sc; acc[q][1] *= sc; acc[q][2] *= sc; acc[q][3] *= sc;
            Ps[(w * 8 + q) * 32 + lane] = p;
        }
        __syncwarp();

        #pragma unroll 8
        for (int j = 0; j < 32; j++) {
            float4 v4 = *(float4*)&Vs[j * 128 + lane * 4];
            #pragma unroll
            for (int q = 0; q < 8; q++) {
                float p = Ps[(w * 8 + q) * 32 + j];
                acc[q][0] += p * v4.x;
                acc[q][1] += p * v4.y;
                acc[q][2] += p * v4.z;
                acc[q][3] += p * v4.w;
            }
        }
    }

    #pragma unroll
    for (int q = 0; q < 8; q++) {
        float inv = 1.f / l[q];
        int qg = qbase + q;
        float4 o4 = make_float4(acc[q][0] * inv, acc[q][1] * inv,
                                acc[q][2] * inv, acc[q][3] * inv);
        *(float4*)&g_o[(size_t)qg * (N_HEADS * V_DIM) + h * V_DIM + lane * 4] = o4;
    }
}

// ---------------------------------------------------------------------------
// Launcher
// ---------------------------------------------------------------------------
extern "C" void kernel_launch(void* const* d_in, const int* in_sizes, int n_in,
                              void* d_out, int out_size) {
    const float* x         = (const float*)d_in[0];
    const float* freqs     = (const float*)d_in[1];
    const float* wq_down   = (const float*)d_in[3];
    const float* q_norm_w  = (const float*)d_in[4];
    const float* wq_nope   = (const float*)d_in[5];
    const float* wq_rope   = (const float*)d_in[6];
    const float* wkv_down  = (const float*)d_in[7];
    const float* kv_norm_w = (const float*)d_in[8];
    const float* wkv_up    = (const float*)d_in[9];
    const float* wo        = (const float*)d_in[10];
    float* out = (float*)d_out;

    float *p_qdt, *p_qlat, *p_qnope, *p_qrope, *p_kvd, *p_ckvn, *p_kvup, *p_o;
    float *p_wqdT, *p_wqnT, *p_wqrT, *p_wkdT, *p_wkuT, *p_woT;
    cudaGetSymbolAddress((void**)&p_qdt,   g_qdt);
    cudaGetSymbolAddress((void**)&p_qlat,  g_qlat);
    cudaGetSymbolAddress((void**)&p_qnope, g_qnope);
    cudaGetSymbolAddress((void**)&p_qrope, g_qrope);
    cudaGetSymbolAddress((void**)&p_kvd,   g_kvd);
    cudaGetSymbolAddress((void**)&p_ckvn,  g_ckvn);
    cudaGetSymbolAddress((void**)&p_kvup,  g_kvup);
    cudaGetSymbolAddress((void**)&p_o,     g_o);
    cudaGetSymbolAddress((void**)&p_wqdT,  g_wqdT);
    cudaGetSymbolAddress((void**)&p_wqnT,  g_wqnT);
    cudaGetSymbolAddress((void**)&p_wqrT,  g_wqrT);
    cudaGetSymbolAddress((void**)&p_wkdT,  g_wkdT);
    cudaGetSymbolAddress((void**)&p_wkuT,  g_wkuT);
    cudaGetSymbolAddress((void**)&p_woT,   g_woT);

    cudaFuncSetAttribute(attn_kernel, cudaFuncAttributeMaxDynamicSharedMemorySize, SMEM_ATTN);

    const dim3 tb(32, 8);
    transpose_tf32<<<dim3(Q_LORA / 32, DIM / 32), tb>>>(wq_down,  p_wqdT, DIM,    Q_LORA, Q_LORA);
    transpose_tf32<<<dim3((N_HEADS*NOPE) / 32, Q_LORA / 32), tb>>>(wq_nope, p_wqnT, Q_LORA, N_HEADS*NOPE, N_HEADS*NOPE);
    transpose_tf32<<<dim3((N_HEADS*ROPE) / 32, Q_LORA / 32), tb>>>(wq_rope, p_wqrT, Q_LORA, N_HEADS*ROPE, N_HEADS*ROPE);
    transpose_tf32<<<dim3(KVD_PAD / 32, DIM / 32), tb>>>(wkv_down, p_wkdT, DIM,   KV_LORA + ROPE, KVD_PAD);
    transpose_tf32<<<dim3((N_HEADS*(NOPE+V_DIM)) / 32, KV_LORA / 32), tb>>>(wkv_up, p_wkuT, KV_LORA, N_HEADS*(NOPE+V_DIM), N_HEADS*(NOPE+V_DIM));
    transpose_tf32<<<dim3(DIM / 32, (N_HEADS*V_DIM) / 32), tb>>>(wo, p_woT, N_HEADS*V_DIM, DIM, DIM);

    const int MB = T_SEQ / 128;   // 24

    mma_gemm<<<dim3(Q_LORA / 128, MB), 256>>>(x, p_wqdT, p_qdt, T_SEQ, Q_LORA, DIM);
    rmsnorm_kernel<<<T_SEQ, 256>>>(p_qdt, q_norm_w, p_qlat, Q_LORA, Q_LORA, Q_LORA);
    mma_gemm<<<dim3((N_HEADS*NOPE) / 128, MB), 256>>>(p_qlat, p_wqnT, p_qnope, T_SEQ, N_HEADS*NOPE, Q_LORA);
    mma_gemm<<<dim3((N_HEADS*ROPE) / 128, MB), 256>>>(p_qlat, p_wqrT, p_qrope, T_SEQ, N_HEADS*ROPE, Q_LORA);
    mma_gemm<<<dim3(KVD_PAD / 128, MB), 256>>>(x, p_wkdT, p_kvd, T_SEQ, KVD_PAD, DIM);
    rmsnorm_kernel<<<T_SEQ, 256>>>(p_kvd, kv_norm_w, p_ckvn, KVD_PAD, KV_LORA, KV_LORA);
    mma_gemm<<<dim3((N_HEADS*(NOPE+V_DIM)) / 128, MB), 256>>>(p_ckvn, p_wkuT, p_kvup, T_SEQ, N_HEADS*(NOPE+V_DIM), KV_LORA);
    assemble_q<<<T_SEQ, 256>>>(freqs);
    assemble_k<<<T_SEQ, 256>>>(freqs);
    attn_kernel<<<dim3(T_SEQ / 64, N_HEADS), 256, SMEM_ATTN>>>();
    mma_gemm<<<dim3(DIM / 128, MB), 256>>>(p_o, p_woT, out, T_SEQ, DIM, DIM);
}

// round 4
// speedup vs baseline: 2.1833x; 1.4841x over previous
#include <cuda_runtime.h>
#include <cuda_bf16.h>
#include <cstdint>
#include <math.h>

// ---------------------------------------------------------------------------
// Problem constants
// ---------------------------------------------------------------------------
#define T_SEQ    3072
#define DIM      2048
#define N_HEADS  16
#define Q_LORA   1536
#define KV_LORA  512
#define NOPE     128
#define ROPE     64
#define V_DIM    128
#define HD       (NOPE + ROPE)       // 192
#define EPS      1e-6f
#define KVD_PAD  640                 // kv_down N=576 padded to 640

__device__ __forceinline__ float to_tf32(float x) {
    uint32_t u; asm("cvt.rna.tf32.f32 %0, %1;" : "=r"(u) : "f"(x));
    return __uint_as_float(u);
}

#define MMA_TF32(d0,d1,d2,d3,a0,a1,a2,a3,b0,b1) \
    asm volatile( \
        "mma.sync.aligned.m16n8k8.row.col.f32.tf32.tf32.f32 " \
        "{%0,%1,%2,%3}, {%4,%5,%6,%7}, {%8,%9}, {%0,%1,%2,%3};" \
        : "+f"(d0), "+f"(d1), "+f"(d2), "+f"(d3) \
        : "r"(a0), "r"(a1), "r"(a2), "r"(a3), "r"(b0), "r"(b1))

// ---------------------------------------------------------------------------
// Scratch (static device globals -- no allocations allowed)
// ---------------------------------------------------------------------------
__device__ float g_qdt  [T_SEQ * Q_LORA];
__device__ float g_qlat [T_SEQ * Q_LORA];
__device__ float g_qnope[T_SEQ * N_HEADS * NOPE];
__device__ float g_qrope[T_SEQ * N_HEADS * ROPE];
__device__ float g_kvd  [T_SEQ * KVD_PAD];
__device__ float g_ckvn [T_SEQ * KV_LORA];
__device__ float g_kvup [T_SEQ * N_HEADS * (NOPE + V_DIM)];
__device__ float g_q    [T_SEQ * N_HEADS * HD];
__device__ float g_k    [T_SEQ * N_HEADS * HD];
__device__ float g_o    [T_SEQ * N_HEADS * V_DIM];

// transposed (K-major [N][K]) tf32-rounded weights
__device__ float g_wqdT [Q_LORA * DIM];
__device__ float g_wqnT [(N_HEADS * NOPE) * Q_LORA];
__device__ float g_wqrT [(N_HEADS * ROPE) * Q_LORA];
__device__ float g_wkdT [KVD_PAD * DIM];
__device__ float g_wkuT [(N_HEADS * (NOPE + V_DIM)) * KV_LORA];
__device__ float g_woT  [DIM * (N_HEADS * V_DIM)];

// ---------------------------------------------------------------------------
// Weight transpose: src[K][N] row-major -> dst[NP][K] (tf32-rounded, zero pad)
// ---------------------------------------------------------------------------
__global__ __launch_bounds__(256)
void transpose_tf32(const float* __restrict__ src, float* __restrict__ dst,
                    int K, int N, int NP) {
    __shared__ float tile[32][33];
    int kb = blockIdx.y * 32, nb = blockIdx.x * 32;
    for (int i = threadIdx.y; i < 32; i += 8) {
        int n = nb + threadIdx.x;
        float v = (n < N) ? src[(size_t)(kb + i) * N + n] : 0.f;
        tile[i][threadIdx.x] = v;
    }
    __syncthreads();
    for (int i = threadIdx.y; i < 32; i += 8) {
        int n = nb + i;
        if (n < NP)
            dst[(size_t)n * K + kb + threadIdx.x] = to_tf32(tile[threadIdx.x][i]);
    }
}

// ---------------------------------------------------------------------------
// TF32 mma.sync GEMM (unchanged from R3, passing)
// ---------------------------------------------------------------------------
#define SMS 20

__global__ __launch_bounds__(256)
void mma_gemm(const float* __restrict__ A, const float* __restrict__ Bt,
              float* __restrict__ C, int M, int N, int K) {
    __shared__ float As[2][128 * SMS];
    __shared__ float Bs[2][128 * SMS];

    const int tid  = threadIdx.x;
    const int wid  = tid >> 5, lane = tid & 31;
    const int gid  = lane >> 2, tig = lane & 3;
    const int wm   = wid >> 2, wn = wid & 3;
    const int bm   = blockIdx.y, bn = blockIdx.x;

    const float* Ab = A  + (size_t)bm * 128 * K;
    const float* Bb = Bt + (size_t)bn * 128 * K;

    const int r  = tid >> 2;
    const int c4 = tid & 3;

    float acc[4][4][4];
    #pragma unroll
    for (int i = 0; i < 4; i++)
        #pragma unroll
        for (int j = 0; j < 4; j++)
            #pragma unroll
            for (int k = 0; k < 4; k++) acc[i][j][k] = 0.f;

    const int nk = K >> 4;

    {
        #pragma unroll
        for (int l = 0; l < 2; l++) {
            int row = r + l * 64;
            float4 va = *(const float4*)&Ab[(size_t)row * K + c4 * 4];
            va.x = to_tf32(va.x); va.y = to_tf32(va.y);
            va.z = to_tf32(va.z); va.w = to_tf32(va.w);
            *(float4*)&As[0][row * SMS + c4 * 4] = va;
            float4 vb = *(const float4*)&Bb[(size_t)row * K + c4 * 4];
            *(float4*)&Bs[0][row * SMS + c4 * 4] = vb;
        }
    }
    __syncthreads();

    for (int kt = 0; kt < nk; kt++) {
        const int cur = kt & 1;

        float4 pa[2], pb[2];
        if (kt + 1 < nk) {
            const int k0 = (kt + 1) * 16;
            #pragma unroll
            for (int l = 0; l < 2; l++) {
                int row = r + l * 64;
                pa[l] = *(const float4*)&Ab[(size_t)row * K + k0 + c4 * 4];
                pb[l] = *(const float4*)&Bb[(size_t)row * K + k0 + c4 * 4];
            }
        }

        const float* as = As[cur];
        const float* bs = Bs[cur];
        #pragma unroll
        for (int ks = 0; ks < 2; ks++) {
            uint32_t a[4][4], b[4][2];
            #pragma unroll
            for (int mf = 0; mf < 4; mf++) {
                int row = wm * 64 + mf * 16 + gid;
                int kk  = ks * 8 + tig;
                a[mf][0] = __float_as_uint(as[row * SMS + kk]);
                a[mf][1] = __float_as_uint(as[(row + 8) * SMS + kk]);
                a[mf][2] = __float_as_uint(as[row * SMS + kk + 4]);
                a[mf][3] = __float_as_uint(as[(row + 8) * SMS + kk + 4]);
            }
            #pragma unroll
            for (int nf = 0; nf < 4; nf++) {
                int col = wn * 32 + nf * 8 + gid;
                int kk  = ks * 8 + tig;
                b[nf][0] = __float_as_uint(bs[col * SMS + kk]);
                b[nf][1] = __float_as_uint(bs[col * SMS + kk + 4]);
            }
            #pragma unroll
            for (int mf = 0; mf < 4; mf++)
                #pragma unroll
                for (int nf = 0; nf < 4; nf++)
                    MMA_TF32(acc[mf][nf][0], acc[mf][nf][1], acc[mf][nf][2], acc[mf][nf][3],
                             a[mf][0], a[mf][1], a[mf][2], a[mf][3],
                             b[nf][0], b[nf][1]);
        }

        if (kt + 1 < nk) {
            const int nxt = cur ^ 1;
            #pragma unroll
            for (int l = 0; l < 2; l++) {
                int row = r + l * 64;
                float4 va = pa[l];
                va.x = to_tf32(va.x); va.y = to_tf32(va.y);
                va.z = to_tf32(va.z); va.w = to_tf32(va.w);
                *(float4*)&As[nxt][row * SMS + c4 * 4] = va;
                *(float4*)&Bs[nxt][row * SMS + c4 * 4] = pb[l];
            }
        }
        __syncthreads();
    }

    #pragma unroll
    for (int mf = 0; mf < 4; mf++) {
        int row0 = bm * 128 + wm * 64 + mf * 16 + gid;
        #pragma unroll
        for (int nf = 0; nf < 4; nf++) {
            int col = bn * 128 + wn * 32 + nf * 8 + tig * 2;
            *(float2*)&C[(size_t)row0 * N + col]       = make_float2(acc[mf][nf][0], acc[mf][nf][1]);
            *(float2*)&C[(size_t)(row0 + 8) * N + col] = make_float2(acc[mf][nf][2], acc[mf][nf][3]);
        }
    }
}

// ---------------------------------------------------------------------------
// Row-wise RMSNorm
// ---------------------------------------------------------------------------
__global__ __launch_bounds__(256)
void rmsnorm_kernel(const float* __restrict__ in, const float* __restrict__ w,
                    float* __restrict__ out, int instride, int outstride, int cols) {
    int r = blockIdx.x;
    const float* row = in + (size_t)r * instride;
    float ss = 0.f;
    for (int c = threadIdx.x; c < cols; c += blockDim.x) {
        float v = row[c];
        ss += v * v;
    }
    __shared__ float red[8];
    int lane = threadIdx.x & 31, wid = threadIdx.x >> 5;
    #pragma unroll
    for (int o = 16; o; o >>= 1) ss += __shfl_xor_sync(0xFFFFFFFFu, ss, o);
    if (lane == 0) red[wid] = ss;
    __syncthreads();
    if (wid == 0) {
        float v = (lane < 8) ? red[lane] : 0.f;
        #pragma unroll
        for (int o = 4; o; o >>= 1) v += __shfl_xor_sync(0xFFFFFFFFu, v, o);
        if (lane == 0) red[0] = v;
    }
    __syncthreads();
    float inv = rsqrtf(red[0] / (float)cols + EPS);
    float* orow = out + (size_t)r * outstride;
    for (int c = threadIdx.x; c < cols; c += blockDim.x)
        orow[c] = row[c] * inv * w[c];
}

// ---------------------------------------------------------------------------
// Assemble Q
// ---------------------------------------------------------------------------
__global__ __launch_bounds__(256)
void assemble_q(const float* __restrict__ freqs) {
    int t = blockIdx.x;
    int tid = threadIdx.x;
    for (int i = tid; i < 512; i += 256) {
        int e = i * 4;
        int h = e >> 7, d = e & 127;
        *(float4*)&g_q[(size_t)t * (N_HEADS * HD) + h * HD + d] =
            *(const float4*)&g_qnope[(size_t)t * (N_HEADS * NOPE) + e];
    }
    for (int i = tid; i < N_HEADS * 32; i += 256) {
        int h = i >> 5, p = i & 31;
        float f = freqs[t * 32 + p];
        float c = cosf(f), s = sinf(f);
        const float* src = &g_qrope[(size_t)t * (N_HEADS * ROPE) + h * ROPE + 2 * p];
        float x1 = src[0], x2 = src[1];
        float* dst = &g_q[(size_t)t * (N_HEADS * HD) + h * HD + NOPE + 2 * p];
        dst[0] = x1 * c - x2 * s;
        dst[1] = x1 * s + x2 * c;
    }
}

// ---------------------------------------------------------------------------
// Assemble K
// ---------------------------------------------------------------------------
__global__ __launch_bounds__(256)
void assemble_k(const float* __restrict__ freqs) {
    int t = blockIdx.x;
    int tid = threadIdx.x;
    for (int i = tid; i < 512; i += 256) {
        int e = i * 4;
        int h = e >> 7, d = e & 127;
        *(float4*)&g_k[(size_t)t * (N_HEADS * HD) + h * HD + d] =
            *(const float4*)&g_kvup[(size_t)t * (N_HEADS * (NOPE + V_DIM)) + h * (NOPE + V_DIM) + d];
    }
    __shared__ float rk[ROPE];
    if (tid < 32) {
        float f = freqs[t * 32 + tid];
        float c = cosf(f), s = sinf(f);
        const float* src = &g_kvd[(size_t)t * KVD_PAD + KV_LORA + 2 * tid];
        float x1 = src[0], x2 = src[1];
        rk[2 * tid]     = x1 * c - x2 * s;
        rk[2 * tid + 1] = x1 * s + x2 * c;
    }
    __syncthreads();
    for (int i = tid; i < N_HEADS * ROPE; i += 256) {
        int h = i >> 6, d = i & 63;
        g_k[(size_t)t * (N_HEADS * HD) + h * HD + NOPE + d] = rk[d];
    }
}

// ---------------------------------------------------------------------------
// Causal flash attention with tf32 mma.sync.
// Grid: (T/64 q-tiles, 16 heads). Block: 256 threads = 8 warps (4 row x 2 col).
// Per key-tile (64 keys):
//   S = Q K^T via MMA -> smem (scaled+masked) -> softmax on smem -> P
//   O += P V via MMA (V stored transposed [vdim][key] in smem)
// ---------------------------------------------------------------------------
#define HDS 196      // Q/K smem row stride (192 + 4)
#define BKS 68       // P / V^T smem row stride (64 + 4)
#define SMEM_ATTN2 ((2 * 64 * HDS + 128 * BKS + 64 * BKS + 3 * 64) * 4)

__global__ __launch_bounds__(256)
void attn_mma() {
    extern __shared__ float sm[];
    float* Qs  = sm;                    // [64][196]
    float* Ks  = Qs  + 64 * HDS;        // [64][196]
    float* VTs = Ks  + 64 * HDS;        // [128][68]  V transposed
    float* Ps  = VTs + 128 * BKS;       // [64][68]   scores / probs
    float* m_s = Ps  + 64 * BKS;        // [64]
    float* l_s = m_s + 64;              // [64]
    float* sc_s= l_s + 64;              // [64]

    const int h   = blockIdx.y;
    const int qt  = blockIdx.x;
    const int tid = threadIdx.x;
    const int wid = tid >> 5, lane = tid & 31;
    const int gid = lane >> 2, tig = lane & 3;
    const int wm  = wid >> 1, wn = wid & 1;
    const int q0  = qt * 64;
    const float scale = 0.07216878364870323f;   // 1/sqrt(192)

    // load Q tile (tf32-rounded)
    for (int i = tid; i < 64 * 48; i += 256) {
        int r = i / 48, c4 = i % 48;
        float4 v = *(const float4*)&g_q[(size_t)(q0 + r) * (N_HEADS * HD) + h * HD + c4 * 4];
        v.x = to_tf32(v.x); v.y = to_tf32(v.y);
        v.z = to_tf32(v.z); v.w = to_tf32(v.w);
        *(float4*)&Qs[r * HDS + c4 * 4] = v;
    }
    if (tid < 64) { m_s[tid] = -1e30f; l_s[tid] = 0.f; }

    float oacc[8][4];
    #pragma unroll
    for (int nf = 0; nf < 8; nf++)
        #pragma unroll
        for (int k = 0; k < 4; k++) oacc[nf][k] = 0.f;

    const int arow = wm * 16 + gid;
    const int ntiles = qt + 1;

    for (int kt = 0; kt < ntiles; kt++) {
        __syncthreads();
        // K tile (tf32-rounded)
        for (int i = tid; i < 64 * 48; i += 256) {
            int r = i / 48, c4 = i % 48;
            float4 v = *(const float4*)&g_k[(size_t)(kt * 64 + r) * (N_HEADS * HD) + h * HD + c4 * 4];
            v.x = to_tf32(v.x); v.y = to_tf32(v.y);
            v.z = to_tf32(v.z); v.w = to_tf32(v.w);
            *(float4*)&Ks[r * HDS + c4 * 4] = v;
        }
        // V tile transposed (tf32-rounded): VTs[d][j]
        for (int i = tid; i < 64 * 32; i += 256) {
            int r = i >> 5, c4 = i & 31;
            float4 v = *(const float4*)&g_kvup[(size_t)(kt * 64 + r) * (N_HEADS * (NOPE + V_DIM))
                                               + h * (NOPE + V_DIM) + NOPE + c4 * 4];
            VTs[(c4 * 4 + 0) * BKS + r] = to_tf32(v.x);
            VTs[(c4 * 4 + 1) * BKS + r] = to_tf32(v.y);
            VTs[(c4 * 4 + 2) * BKS + r] = to_tf32(v.z);
            VTs[(c4 * 4 + 3) * BKS + r] = to_tf32(v.w);
        }
        __syncthreads();

        // S = Q K^T : warp tile 16 x 32
        float sacc[4][4];
        #pragma unroll
        for (int nf = 0; nf < 4; nf++)
            #pragma unroll
            for (int k = 0; k < 4; k++) sacc[nf][k] = 0.f;

        #pragma unroll 6
        for (int ks = 0; ks < 24; ks++) {
            const int kk = ks * 8 + tig;
            uint32_t a0 = __float_as_uint(Qs[arow * HDS + kk]);
            uint32_t a1 = __float_as_uint(Qs[(arow + 8) * HDS + kk]);
            uint32_t a2 = __float_as_uint(Qs[arow * HDS + kk + 4]);
            uint32_t a3 = __float_as_uint(Qs[(arow + 8) * HDS + kk + 4]);
            #pragma unroll
            for (int nf = 0; nf < 4; nf++) {
                int col = wn * 32 + nf * 8 + gid;
                uint32_t b0 = __float_as_uint(Ks[col * HDS + kk]);
                uint32_t b1 = __float_as_uint(Ks[col * HDS + kk + 4]);
                MMA_TF32(sacc[nf][0], sacc[nf][1], sacc[nf][2], sacc[nf][3],
                         a0, a1, a2, a3, b0, b1);
            }
        }

        // write scaled + masked scores to Ps
        {
            const int r0 = wm * 16 + gid, r1 = r0 + 8;
            const int qg0 = q0 + r0, qg1 = q0 + r1;
            #pragma unroll
            for (int nf = 0; nf < 4; nf++) {
                int col = wn * 32 + nf * 8 + tig * 2;
                int jg  = kt * 64 + col;
                float v0 = (jg     <= qg0) ? sacc[nf][0] * scale : -1e30f;
                float v1 = (jg + 1 <= qg0) ? sacc[nf][1] * scale : -1e30f;
                float v2 = (jg     <= qg1) ? sacc[nf][2] * scale : -1e30f;
                float v3 = (jg + 1 <= qg1) ? sacc[nf][3] * scale : -1e30f;
                *(float2*)&Ps[r0 * BKS + col] = make_float2(v0, v1);
                *(float2*)&Ps[r1 * BKS + col] = make_float2(v2, v3);
            }
        }
        __syncthreads();

        // softmax on Ps: 4 threads per row, 16 cols each
        {
            const int row = tid >> 2, t4 = tid & 3;
            float* prow = &Ps[row * BKS + t4 * 16];
            float4 x0 = *(float4*)&prow[0];
            float4 x1 = *(float4*)&prow[4];
            float4 x2 = *(float4*)&prow[8];
            float4 x3 = *(float4*)&prow[12];
            float tmax = fmaxf(fmaxf(fmaxf(x0.x, x0.y), fmaxf(x0.z, x0.w)),
                        fmaxf(fmaxf(fmaxf(x1.x, x1.y), fmaxf(x1.z, x1.w)),
                        fmaxf(fmaxf(fmaxf(x2.x, x2.y), fmaxf(x2.z, x2.w)),
                              fmaxf(fmaxf(x3.x, x3.y), fmaxf(x3.z, x3.w)))));
            tmax = fmaxf(tmax, __shfl_xor_sync(0xFFFFFFFFu, tmax, 1));
            tmax = fmaxf(tmax, __shfl_xor_sync(0xFFFFFFFFu, tmax, 2));
            float mo = m_s[row];
            float nm = fmaxf(mo, tmax);
            float sc = __expf(mo - nm);
            float s = 0.f;
            x0.x = to_tf32(__expf(x0.x - nm)); s += x0.x;
            x0.y = to_tf32(__expf(x0.y - nm)); s += x0.y;
            x0.z = to_tf32(__expf(x0.z - nm)); s += x0.z;
            x0.w = to_tf32(__expf(x0.w - nm)); s += x0.w;
            x1.x = to_tf32(__expf(x1.x - nm)); s += x1.x;
            x1.y = to_tf32(__expf(x1.y - nm)); s += x1.y;
            x1.z = to_tf32(__expf(x1.z - nm)); s += x1.z;
            x1.w = to_tf32(__expf(x1.w - nm)); s += x1.w;
            x2.x = to_tf32(__expf(x2.x - nm)); s += x2.x;
            x2.y = to_tf32(__expf(x2.y - nm)); s += x2.y;
            x2.z = to_tf32(__expf(x2.z - nm)); s += x2.z;
            x2.w = to_tf32(__expf(x2.w - nm)); s += x2.w;
            x3.x = to_tf32(__expf(x3.x - nm)); s += x3.x;
            x3.y = to_tf32(__expf(x3.y - nm)); s += x3.y;
            x3.z = to_tf32(__expf(x3.z - nm)); s += x3.z;
            x3.w = to_tf32(__expf(x3.w - nm)); s += x3.w;
            *(float4*)&prow[0]  = x0;
            *(float4*)&prow[4]  = x1;
            *(float4*)&prow[8]  = x2;
            *(float4*)&prow[12] = x3;
            s += __shfl_xor_sync(0xFFFFFFFFu, s, 1);
            s += __shfl_xor_sync(0xFFFFFFFFu, s, 2);
            if (t4 == 0) {
                l_s[row] = l_s[row] * sc + s;
                m_s[row] = nm;
                sc_s[row] = sc;
            }
        }
        __syncthreads();

        // rescale O accumulators and do O += P V
        {
            float sc0 = sc_s[arow], sc1 = sc_s[arow + 8];
            #pragma unroll
            for (int nf = 0; nf < 8; nf++) {
                oacc[nf][0] *= sc0; oacc[nf][1] *= sc0;
                oacc[nf][2] *= sc1; oacc[nf][3] *= sc1;
            }
            #pragma unroll
            for (int ks = 0; ks < 8; ks++) {
                const int kk = ks * 8 + tig;
                uint32_t a0 = __float_as_uint(Ps[arow * BKS + kk]);
                uint32_t a1 = __float_as_uint(Ps[(arow + 8) * BKS + kk]);
                uint32_t a2 = __float_as_uint(Ps[arow * BKS + kk + 4]);
                uint32_t a3 = __float_as_uint(Ps[(arow + 8) * BKS + kk + 4]);
                #pragma unroll
                for (int nf = 0; nf < 8; nf++) {
                    int col = wn * 64 + nf * 8 + gid;
                    uint32_t b0 = __float_as_uint(VTs[col * BKS + kk]);
                    uint32_t b1 = __float_as_uint(VTs[col * BKS + kk + 4]);
                    MMA_TF32(oacc[nf][0], oacc[nf][1], oacc[nf][2], oacc[nf][3],
                             a0, a1, a2, a3, b0, b1);
                }
            }
        }
    }

    // epilogue: O / l
    {
        float li0 = 1.f / l_s[arow];
        float li1 = 1.f / l_s[arow + 8];
        const int row0 = q0 + arow;
        #pragma unroll
        for (int nf = 0; nf < 8; nf++) {
            int col = wn * 64 + nf * 8 + tig * 2;
            *(float2*)&g_o[(size_t)row0 * (N_HEADS * V_DIM) + h * V_DIM + col] =
                make_float2(oacc[nf][0] * li0, oacc[nf][1] * li0);
            *(float2*)&g_o[(size_t)(row0 + 8) * (N_HEADS * V_DIM) + h * V_DIM + col] =
                make_float2(oacc[nf][2] * li1, oacc[nf][3] * li1);
        }
    }
}

// ---------------------------------------------------------------------------
// Launcher
// ---------------------------------------------------------------------------
extern "C" void kernel_launch(void* const* d_in, const int* in_sizes, int n_in,
                              void* d_out, int out_size) {
    const float* x         = (const float*)d_in[0];
    const float* freqs     = (const float*)d_in[1];
    const float* wq_down   = (const float*)d_in[3];
    const float* q_norm_w  = (const float*)d_in[4];
    const float* wq_nope   = (const float*)d_in[5];
    const float* wq_rope   = (const float*)d_in[6];
    const float* wkv_down  = (const float*)d_in[7];
    const float* kv_norm_w = (const float*)d_in[8];
    const float* wkv_up    = (const float*)d_in[9];
    const float* wo        = (const float*)d_in[10];
    float* out = (float*)d_out;

    float *p_qdt, *p_qlat, *p_qnope, *p_qrope, *p_kvd, *p_ckvn, *p_kvup, *p_o;
    float *p_wqdT, *p_wqnT, *p_wqrT, *p_wkdT, *p_wkuT, *p_woT;
    cudaGetSymbolAddress((void**)&p_qdt,   g_qdt);
    cudaGetSymbolAddress((void**)&p_qlat,  g_qlat);
    cudaGetSymbolAddress((void**)&p_qnope, g_qnope);
    cudaGetSymbolAddress((void**)&p_qrope, g_qrope);
    cudaGetSymbolAddress((void**)&p_kvd,   g_kvd);
    cudaGetSymbolAddress((void**)&p_ckvn,  g_ckvn);
    cudaGetSymbolAddress((void**)&p_kvup,  g_kvup);
    cudaGetSymbolAddress((void**)&p_o,     g_o);
    cudaGetSymbolAddress((void**)&p_wqdT,  g_wqdT);
    cudaGetSymbolAddress((void**)&p_wqnT,  g_wqnT);
    cudaGetSymbolAddress((void**)&p_wqrT,  g_wqrT);
    cudaGetSymbolAddress((void**)&p_wkdT,  g_wkdT);
    cudaGetSymbolAddress((void**)&p_wkuT,  g_wkuT);
    cudaGetSymbolAddress((void**)&p_woT,   g_woT);

    cudaFuncSetAttribute(attn_mma, cudaFuncAttributeMaxDynamicSharedMemorySize, SMEM_ATTN2);

    const dim3 tb(32, 8);
    transpose_tf32<<<dim3(Q_LORA / 32, DIM / 32), tb>>>(wq_down,  p_wqdT, DIM,    Q_LORA, Q_LORA);
    transpose_tf32<<<dim3((N_HEADS*NOPE) / 32, Q_LORA / 32), tb>>>(wq_nope, p_wqnT, Q_LORA, N_HEADS*NOPE, N_HEADS*NOPE);
    transpose_tf32<<<dim3((N_HEADS*ROPE) / 32, Q_LORA / 32), tb>>>(wq_rope, p_wqrT, Q_LORA, N_HEADS*ROPE, N_HEADS*ROPE);
    transpose_tf32<<<dim3(KVD_PAD / 32, DIM / 32), tb>>>(wkv_down, p_wkdT, DIM,   KV_LORA + ROPE, KVD_PAD);
    transpose_tf32<<<dim3((N_HEADS*(NOPE+V_DIM)) / 32, KV_LORA / 32), tb>>>(wkv_up, p_wkuT, KV_LORA, N_HEADS*(NOPE+V_DIM), N_HEADS*(NOPE+V_DIM));
    transpose_tf32<<<dim3(DIM / 32, (N_HEADS*V_DIM) / 32), tb>>>(wo, p_woT, N_HEADS*V_DIM, DIM, DIM);

    const int MB = T_SEQ / 128;   // 24

    mma_gemm<<<dim3(Q_LORA / 128, MB), 256>>>(x, p_wqdT, p_qdt, T_SEQ, Q_LORA, DIM);
    rmsnorm_kernel<<<T_SEQ, 256>>>(p_qdt, q_norm_w, p_qlat, Q_LORA, Q_LORA, Q_LORA);
    mma_gemm<<<dim3((N_HEADS*NOPE) / 128, MB), 256>>>(p_qlat, p_wqnT, p_qnope, T_SEQ, N_HEADS*NOPE, Q_LORA);
    mma_gemm<<<dim3((N_HEADS*ROPE) / 128, MB), 256>>>(p_qlat, p_wqrT, p_qrope, T_SEQ, N_HEADS*ROPE, Q_LORA);
    mma_gemm<<<dim3(KVD_PAD / 128, MB), 256>>>(x, p_wkdT, p_kvd, T_SEQ, KVD_PAD, DIM);
    rmsnorm_kernel<<<T_SEQ, 256>>>(p_kvd, kv_norm_w, p_ckvn, KVD_PAD, KV_LORA, KV_LORA);
    mma_gemm<<<dim3((N_HEADS*(NOPE+V_DIM)) / 128, MB), 256>>>(p_ckvn, p_wkuT, p_kvup, T_SEQ, N_HEADS*(NOPE+V_DIM), KV_LORA);
    assemble_q<<<T_SEQ, 256>>>(freqs);
    assemble_k<<<T_SEQ, 256>>>(freqs);
    attn_mma<<<dim3(T_SEQ / 64, N_HEADS), 256, SMEM_ATTN2>>>();
    mma_gemm<<<dim3(DIM / 128, MB), 256>>>(p_o, p_woT, out, T_SEQ, DIM, DIM);
}

// round 5
// speedup vs baseline: 2.3208x; 1.0630x over previous
#include <cuda_runtime.h>
#include <cuda_bf16.h>
#include <cstdint>
#include <math.h>

// ---------------------------------------------------------------------------
// Problem constants
// ---------------------------------------------------------------------------
#define T_SEQ    3072
#define DIM      2048
#define N_HEADS  16
#define Q_LORA   1536
#define KV_LORA  512
#define NOPE     128
#define ROPE     64
#define V_DIM    128
#define HD       (NOPE + ROPE)       // 192
#define EPS      1e-6f
#define KVD_PAD  640                 // kv_down N=576 padded to 640

__device__ __forceinline__ float to_tf32(float x) {
    uint32_t u; asm("cvt.rna.tf32.f32 %0, %1;" : "=r"(u) : "f"(x));
    return __uint_as_float(u);
}
__device__ __forceinline__ uint32_t smem_u32(const void* p) {
    uint32_t a;
    asm("{ .reg .u64 t; cvta.to.shared.u64 t, %1; cvt.u32.u64 %0, t; }" : "=r"(a) : "l"(p));
    return a;
}
__device__ __forceinline__ void cp_async16(uint32_t saddr, const void* gptr) {
    asm volatile("cp.async.cg.shared.global [%0], [%1], 16;" :: "r"(saddr), "l"(gptr));
}
#define CP_COMMIT() asm volatile("cp.async.commit_group;")
#define CP_WAIT(n)  asm volatile("cp.async.wait_group %0;" :: "n"(n))

#define MMA_TF32(d0,d1,d2,d3,a0,a1,a2,a3,b0,b1) \
    asm volatile( \
        "mma.sync.aligned.m16n8k8.row.col.f32.tf32.tf32.f32 " \
        "{%0,%1,%2,%3}, {%4,%5,%6,%7}, {%8,%9}, {%0,%1,%2,%3};" \
        : "+f"(d0), "+f"(d1), "+f"(d2), "+f"(d3) \
        : "r"(a0), "r"(a1), "r"(a2), "r"(a3), "r"(b0), "r"(b1))

// ---------------------------------------------------------------------------
// Scratch (static device globals -- no allocations allowed)
// ---------------------------------------------------------------------------
__device__ float g_xr   [T_SEQ * DIM];                // tf32-rounded x
__device__ float g_qdt  [T_SEQ * Q_LORA];
__device__ float g_qlat [T_SEQ * Q_LORA];             // tf32-rounded
__device__ float g_qnope[T_SEQ * N_HEADS * NOPE];
__device__ float g_qrope[T_SEQ * N_HEADS * ROPE];
__device__ float g_kvd  [T_SEQ * KVD_PAD];
__device__ float g_ckvn [T_SEQ * KV_LORA];            // tf32-rounded
__device__ float g_kvup [T_SEQ * N_HEADS * (NOPE + V_DIM)];
__device__ float g_q    [T_SEQ * N_HEADS * HD];
__device__ float g_k    [T_SEQ * N_HEADS * HD];
__device__ float g_o    [T_SEQ * N_HEADS * V_DIM];    // tf32-rounded

// transposed (K-major [N][K]) tf32-rounded weights
__device__ float g_wqdT [Q_LORA * DIM];
__device__ float g_wqnT [(N_HEADS * NOPE) * Q_LORA];
__device__ float g_wqrT [(N_HEADS * ROPE) * Q_LORA];
__device__ float g_wkdT [KVD_PAD * DIM];
__device__ float g_wkuT [(N_HEADS * (NOPE + V_DIM)) * KV_LORA];
__device__ float g_woT  [DIM * (N_HEADS * V_DIM)];

// ---------------------------------------------------------------------------
// Round a fp32 buffer to tf32 (vectorized)
// ---------------------------------------------------------------------------
__global__ __launch_bounds__(256)
void round_tf32_kernel(const float* __restrict__ src, float* __restrict__ dst, int n4) {
    int i = blockIdx.x * 256 + threadIdx.x;
    if (i < n4) {
        float4 v = *(const float4*)&src[i * 4];
        v.x = to_tf32(v.x); v.y = to_tf32(v.y);
        v.z = to_tf32(v.z); v.w = to_tf32(v.w);
        *(float4*)&dst[i * 4] = v;
    }
}

// ---------------------------------------------------------------------------
// Weight transpose: src[K][N] row-major -> dst[NP][K] (tf32-rounded, zero pad)
// ---------------------------------------------------------------------------
__global__ __launch_bounds__(256)
void transpose_tf32(const float* __restrict__ src, float* __restrict__ dst,
                    int K, int N, int NP) {
    __shared__ float tile[32][33];
    int kb = blockIdx.y * 32, nb = blockIdx.x * 32;
    for (int i = threadIdx.y; i < 32; i += 8) {
        int n = nb + threadIdx.x;
        float v = (n < N) ? src[(size_t)(kb + i) * N + n] : 0.f;
        tile[i][threadIdx.x] = v;
    }
    __syncthreads();
    for (int i = threadIdx.y; i < 32; i += 8) {
        int n = nb + i;
        if (n < NP)
            dst[(size_t)n * K + kb + threadIdx.x] = to_tf32(tile[threadIdx.x][i]);
    }
}

// ---------------------------------------------------------------------------
// TF32 mma.sync GEMM v2: 3-stage cp.async pipeline.
// CTA 128x128, 128 threads (4 warps, 2x2 of 64x64 warp tiles), BK=16/stage.
// A: row-major [M][K] tf32-rounded. Bt: [N][K] tf32-rounded.
// C = A @ Bt^T. Requires M%128==0, N%128==0, K%16==0, K/16 >= 2.
// ---------------------------------------------------------------------------
#define SMS 20
#define STAGES 3
#define TILE_ELEMS (128 * SMS)
#define GEMM_SMEM (STAGES * 2 * TILE_ELEMS * 4)

__global__ __launch_bounds__(128)
void mma_gemm(const float* __restrict__ A, const float* __restrict__ Bt,
              float* __restrict__ C, int M, int N, int K) {
    extern __shared__ float sh[];
    float* AsAll = sh;
    float* BsAll = sh + STAGES * TILE_ELEMS;
    const uint32_t as_base = smem_u32(AsAll);
    const uint32_t bs_base = smem_u32(BsAll);

    const int tid  = threadIdx.x;
    const int wid  = tid >> 5, lane = tid & 31;
    const int gid  = lane >> 2, tig = lane & 3;
    const int wm   = wid >> 1, wn = wid & 1;
    const int bm   = blockIdx.y, bn = blockIdx.x;

    const float* Ab = A  + (size_t)bm * 128 * K;
    const float* Bb = Bt + (size_t)bn * 128 * K;

    const int lrow = tid >> 2;          // 0..31
    const int lc4  = tid & 3;           // 0..3

    float acc[4][8][4];
    #pragma unroll
    for (int i = 0; i < 4; i++)
        #pragma unroll
        for (int j = 0; j < 8; j++)
            #pragma unroll
            for (int k = 0; k < 4; k++) acc[i][j][k] = 0.f;

    const int nk = K >> 4;

    // prologue: issue first STAGES-1 tiles
    #pragma unroll
    for (int s = 0; s < STAGES - 1; s++) {
        const int k0 = s * 16;
        #pragma unroll
        for (int l = 0; l < 4; l++) {
            int row = lrow + l * 32;
            uint32_t soff = (uint32_t)(s * TILE_ELEMS + row * SMS + lc4 * 4) * 4;
            cp_async16(as_base + soff, &Ab[(size_t)row * K + k0 + lc4 * 4]);
            cp_async16(bs_base + soff, &Bb[(size_t)row * K + k0 + lc4 * 4]);
        }
        CP_COMMIT();
    }

    for (int kt = 0; kt < nk; kt++) {
        CP_WAIT(STAGES - 2);
        __syncthreads();

        // issue tile kt + STAGES-1 into buffer (kt+STAGES-1)%STAGES
        if (kt + STAGES - 1 < nk) {
            const int s = (kt + STAGES - 1) % STAGES;
            const int k0 = (kt + STAGES - 1) * 16;
            #pragma unroll
            for (int l = 0; l < 4; l++) {
                int row = lrow + l * 32;
                uint32_t soff = (uint32_t)(s * TILE_ELEMS + row * SMS + lc4 * 4) * 4;
                cp_async16(as_base + soff, &Ab[(size_t)row * K + k0 + lc4 * 4]);
                cp_async16(bs_base + soff, &Bb[(size_t)row * K + k0 + lc4 * 4]);
            }
        }
        CP_COMMIT();

        // compute on buffer kt % STAGES
        const float* as = AsAll + (kt % STAGES) * TILE_ELEMS;
        const float* bs = BsAll + (kt % STAGES) * TILE_ELEMS;
        #pragma unroll
        for (int ks = 0; ks < 2; ks++) {
            const int kk = ks * 8 + tig;
            uint32_t a[4][4], b[8][2];
            #pragma unroll
            for (int mf = 0; mf < 4; mf++) {
                int row = wm * 64 + mf * 16 + gid;
                a[mf][0] = __float_as_uint(as[row * SMS + kk]);
                a[mf][1] = __float_as_uint(as[(row + 8) * SMS + kk]);
                a[mf][2] = __float_as_uint(as[row * SMS + kk + 4]);
                a[mf][3] = __float_as_uint(as[(row + 8) * SMS + kk + 4]);
            }
            #pragma unroll
            for (int nf = 0; nf < 8; nf++) {
                int col = wn * 64 + nf * 8 + gid;
                b[nf][0] = __float_as_uint(bs[col * SMS + kk]);
                b[nf][1] = __float_as_uint(bs[col * SMS + kk + 4]);
            }
            #pragma unroll
            for (int mf = 0; mf < 4; mf++)
                #pragma unroll
                for (int nf = 0; nf < 8; nf++)
                    MMA_TF32(acc[mf][nf][0], acc[mf][nf][1], acc[mf][nf][2], acc[mf][nf][3],
                             a[mf][0], a[mf][1], a[mf][2], a[mf][3],
                             b[nf][0], b[nf][1]);
        }
    }

    // epilogue
    #pragma unroll
    for (int mf = 0; mf < 4; mf++) {
        int row0 = bm * 128 + wm * 64 + mf * 16 + gid;
        #pragma unroll
        for (int nf = 0; nf < 8; nf++) {
            int col = bn * 128 + wn * 64 + nf * 8 + tig * 2;
            *(float2*)&C[(size_t)row0 * N + col]       = make_float2(acc[mf][nf][0], acc[mf][nf][1]);
            *(float2*)&C[(size_t)(row0 + 8) * N + col] = make_float2(acc[mf][nf][2], acc[mf][nf][3]);
        }
    }
}

// ---------------------------------------------------------------------------
// Row-wise RMSNorm (outputs tf32-rounded)
// ---------------------------------------------------------------------------
__global__ __launch_bounds__(256)
void rmsnorm_kernel(const float* __restrict__ in, const float* __restrict__ w,
                    float* __restrict__ out, int instride, int outstride, int cols) {
    int r = blockIdx.x;
    const float* row = in + (size_t)r * instride;
    float ss = 0.f;
    for (int c = threadIdx.x; c < cols; c += blockDim.x) {
        float v = row[c];
        ss += v * v;
    }
    __shared__ float red[8];
    int lane = threadIdx.x & 31, wid = threadIdx.x >> 5;
    #pragma unroll
    for (int o = 16; o; o >>= 1) ss += __shfl_xor_sync(0xFFFFFFFFu, ss, o);
    if (lane == 0) red[wid] = ss;
    __syncthreads();
    if (wid == 0) {
        float v = (lane < 8) ? red[lane] : 0.f;
        #pragma unroll
        for (int o = 4; o; o >>= 1) v += __shfl_xor_sync(0xFFFFFFFFu, v, o);
        if (lane == 0) red[0] = v;
    }
    __syncthreads();
    float inv = rsqrtf(red[0] / (float)cols + EPS);
    float* orow = out + (size_t)r * outstride;
    for (int c = threadIdx.x; c < cols; c += blockDim.x)
        orow[c] = to_tf32(row[c] * inv * w[c]);
}

// ---------------------------------------------------------------------------
// Assemble Q
// ---------------------------------------------------------------------------
__global__ __launch_bounds__(256)
void assemble_q(const float* __restrict__ freqs) {
    int t = blockIdx.x;
    int tid = threadIdx.x;
    for (int i = tid; i < 512; i += 256) {
        int e = i * 4;
        int h = e >> 7, d = e & 127;
        *(float4*)&g_q[(size_t)t * (N_HEADS * HD) + h * HD + d] =
            *(const float4*)&g_qnope[(size_t)t * (N_HEADS * NOPE) + e];
    }
    for (int i = tid; i < N_HEADS * 32; i += 256) {
        int h = i >> 5, p = i & 31;
        float f = freqs[t * 32 + p];
        float c = cosf(f), s = sinf(f);
        const float* src = &g_qrope[(size_t)t * (N_HEADS * ROPE) + h * ROPE + 2 * p];
        float x1 = src[0], x2 = src[1];
        float* dst = &g_q[(size_t)t * (N_HEADS * HD) + h * HD + NOPE + 2 * p];
        dst[0] = x1 * c - x2 * s;
        dst[1] = x1 * s + x2 * c;
    }
}

// ---------------------------------------------------------------------------
// Assemble K
// ---------------------------------------------------------------------------
__global__ __launch_bounds__(256)
void assemble_k(const float* __restrict__ freqs) {
    int t = blockIdx.x;
    int tid = threadIdx.x;
    for (int i = tid; i < 512; i += 256) {
        int e = i * 4;
        int h = e >> 7, d = e & 127;
        *(float4*)&g_k[(size_t)t * (N_HEADS * HD) + h * HD + d] =
            *(const float4*)&g_kvup[(size_t)t * (N_HEADS * (NOPE + V_DIM)) + h * (NOPE + V_DIM) + d];
    }
    __shared__ float rk[ROPE];
    if (tid < 32) {
        float f = freqs[t * 32 + tid];
        float c = cosf(f), s = sinf(f);
        const float* src = &g_kvd[(size_t)t * KVD_PAD + KV_LORA + 2 * tid];
        float x1 = src[0], x2 = src[1];
        rk[2 * tid]     = x1 * c - x2 * s;
        rk[2 * tid + 1] = x1 * s + x2 * c;
    }
    __syncthreads();
    for (int i = tid; i < N_HEADS * ROPE; i += 256) {
        int h = i >> 6, d = i & 63;
        g_k[(size_t)t * (N_HEADS * HD) + h * HD + NOPE + d] = rk[d];
    }
}

// ---------------------------------------------------------------------------
// Causal flash attention with tf32 mma.sync (R4, proven; epilogue now rounds)
// ---------------------------------------------------------------------------
#define HDS 196
#define BKS 68
#define SMEM_ATTN2 ((2 * 64 * HDS + 128 * BKS + 64 * BKS + 3 * 64) * 4)

__global__ __launch_bounds__(256)
void attn_mma() {
    extern __shared__ float sm[];
    float* Qs  = sm;
    float* Ks  = Qs  + 64 * HDS;
    float* VTs = Ks  + 64 * HDS;
    float* Ps  = VTs + 128 * BKS;
    float* m_s = Ps  + 64 * BKS;
    float* l_s = m_s + 64;
    float* sc_s= l_s + 64;

    const int h   = blockIdx.y;
    const int qt  = blockIdx.x;
    const int tid = threadIdx.x;
    const int wid = tid >> 5, lane = tid & 31;
    const int gid = lane >> 2, tig = lane & 3;
    const int wm  = wid >> 1, wn = wid & 1;
    const int q0  = qt * 64;
    const float scale = 0.07216878364870323f;

    for (int i = tid; i < 64 * 48; i += 256) {
        int r = i / 48, c4 = i % 48;
        float4 v = *(const float4*)&g_q[(size_t)(q0 + r) * (N_HEADS * HD) + h * HD + c4 * 4];
        v.x = to_tf32(v.x); v.y = to_tf32(v.y);
        v.z = to_tf32(v.z); v.w = to_tf32(v.w);
        *(float4*)&Qs[r * HDS + c4 * 4] = v;
    }
    if (tid < 64) { m_s[tid] = -1e30f; l_s[tid] = 0.f; }

    float oacc[8][4];
    #pragma unroll
    for (int nf = 0; nf < 8; nf++)
        #pragma unroll
        for (int k = 0; k < 4; k++) oacc[nf][k] = 0.f;

    const int arow = wm * 16 + gid;
    const int ntiles = qt + 1;

    for (int kt = 0; kt < ntiles; kt++) {
        __syncthreads();
        for (int i = tid; i < 64 * 48; i += 256) {
            int r = i / 48, c4 = i % 48;
            float4 v = *(const float4*)&g_k[(size_t)(kt * 64 + r) * (N_HEADS * HD) + h * HD + c4 * 4];
            v.x = to_tf32(v.x); v.y = to_tf32(v.y);
            v.z = to_tf32(v.z); v.w = to_tf32(v.w);
            *(float4*)&Ks[r * HDS + c4 * 4] = v;
        }
        for (int i = tid; i < 64 * 32; i += 256) {
            int r = i >> 5, c4 = i & 31;
            float4 v = *(const float4*)&g_kvup[(size_t)(kt * 64 + r) * (N_HEADS * (NOPE + V_DIM))
                                               + h * (NOPE + V_DIM) + NOPE + c4 * 4];
            VTs[(c4 * 4 + 0) * BKS + r] = to_tf32(v.x);
            VTs[(c4 * 4 + 1) * BKS + r] = to_tf32(v.y);
            VTs[(c4 * 4 + 2) * BKS + r] = to_tf32(v.z);
            VTs[(c4 * 4 + 3) * BKS + r] = to_tf32(v.w);
        }
        __syncthreads();

        float sacc[4][4];
        #pragma unroll
        for (int nf = 0; nf < 4; nf++)
            #pragma unroll
            for (int k = 0; k < 4; k++) sacc[nf][k] = 0.f;

        #pragma unroll 6
        for (int ks = 0; ks < 24; ks++) {
            const int kk = ks * 8 + tig;
            uint32_t a0 = __float_as_uint(Qs[arow * HDS + kk]);
            uint32_t a1 = __float_as_uint(Qs[(arow + 8) * HDS + kk]);
            uint32_t a2 = __float_as_uint(Qs[arow * HDS + kk + 4]);
            uint32_t a3 = __float_as_uint(Qs[(arow + 8) * HDS + kk + 4]);
            #pragma unroll
            for (int nf = 0; nf < 4; nf++) {
                int col = wn * 32 + nf * 8 + gid;
                uint32_t b0 = __float_as_uint(Ks[col * HDS + kk]);
                uint32_t b1 = __float_as_uint(Ks[col * HDS + kk + 4]);
                MMA_TF32(sacc[nf][0], sacc[nf][1], sacc[nf][2], sacc[nf][3],
                         a0, a1, a2, a3, b0, b1);
            }
        }

        {
            const int r0 = wm * 16 + gid, r1 = r0 + 8;
            const int qg0 = q0 + r0, qg1 = q0 + r1;
            #pragma unroll
            for (int nf = 0; nf < 4; nf++) {
                int col = wn * 32 + nf * 8 + tig * 2;
                int jg  = kt * 64 + col;
                float v0 = (jg     <= qg0) ? sacc[nf][0] * scale : -1e30f;
                float v1 = (jg + 1 <= qg0) ? sacc[nf][1] * scale : -1e30f;
                float v2 = (jg     <= qg1) ? sacc[nf][2] * scale : -1e30f;
                float v3 = (jg + 1 <= qg1) ? sacc[nf][3] * scale : -1e30f;
                *(float2*)&Ps[r0 * BKS + col] = make_float2(v0, v1);
                *(float2*)&Ps[r1 * BKS + col] = make_float2(v2, v3);
            }
        }
        __syncthreads();

        {
            const int row = tid >> 2, t4 = tid & 3;
            float* prow = &Ps[row * BKS + t4 * 16];
            float4 x0 = *(float4*)&prow[0];
            float4 x1 = *(float4*)&prow[4];
            float4 x2 = *(float4*)&prow[8];
            float4 x3 = *(float4*)&prow[12];
            float tmax = fmaxf(fmaxf(fmaxf(x0.x, x0.y), fmaxf(x0.z, x0.w)),
                        fmaxf(fmaxf(fmaxf(x1.x, x1.y), fmaxf(x1.z, x1.w)),
                        fmaxf(fmaxf(fmaxf(x2.x, x2.y), fmaxf(x2.z, x2.w)),
                              fmaxf(fmaxf(x3.x, x3.y), fmaxf(x3.z, x3.w)))));
            tmax = fmaxf(tmax, __shfl_xor_sync(0xFFFFFFFFu, tmax, 1));
            tmax = fmaxf(tmax, __shfl_xor_sync(0xFFFFFFFFu, tmax, 2));
            float mo = m_s[row];
            float nm = fmaxf(mo, tmax);
            float sc = __expf(mo - nm);
            float s = 0.f;
            x0.x = to_tf32(__expf(x0.x - nm)); s += x0.x;
            x0.y = to_tf32(__expf(x0.y - nm)); s += x0.y;
            x0.z = to_tf32(__expf(x0.z - nm)); s += x0.z;
            x0.w = to_tf32(__expf(x0.w - nm)); s += x0.w;
            x1.x = to_tf32(__expf(x1.x - nm)); s += x1.x;
            x1.y = to_tf32(__expf(x1.y - nm)); s += x1.y;
            x1.z = to_tf32(__expf(x1.z - nm)); s += x1.z;
            x1.w = to_tf32(__expf(x1.w - nm)); s += x1.w;
            x2.x = to_tf32(__expf(x2.x - nm)); s += x2.x;
            x2.y = to_tf32(__expf(x2.y - nm)); s += x2.y;
            x2.z = to_tf32(__expf(x2.z - nm)); s += x2.z;
            x2.w = to_tf32(__expf(x2.w - nm)); s += x2.w;
            x3.x = to_tf32(__expf(x3.x - nm)); s += x3.x;
            x3.y = to_tf32(__expf(x3.y - nm)); s += x3.y;
            x3.z = to_tf32(__expf(x3.z - nm)); s += x3.z;
            x3.w = to_tf32(__expf(x3.w - nm)); s += x3.w;
            *(float4*)&prow[0]  = x0;
            *(float4*)&prow[4]  = x1;
            *(float4*)&prow[8]  = x2;
            *(float4*)&prow[12] = x3;
            s += __shfl_xor_sync(0xFFFFFFFFu, s, 1);
            s += __shfl_xor_sync(0xFFFFFFFFu, s, 2);
            if (t4 == 0) {
                l_s[row] = l_s[row] * sc + s;
                m_s[row] = nm;
                sc_s[row] = sc;
            }
        }
        __syncthreads();

        {
            float sc0 = sc_s[arow], sc1 = sc_s[arow + 8];
            #pragma unroll
            for (int nf = 0; nf < 8; nf++) {
                oacc[nf][0] *= sc0; oacc[nf][1] *= sc0;
                oacc[nf][2] *= sc1; oacc[nf][3] *= sc1;
            }
            #pragma unroll
            for (int ks = 0; ks < 8; ks++) {
                const int kk = ks * 8 + tig;
                uint32_t a0 = __float_as_uint(Ps[arow * BKS + kk]);
                uint32_t a1 = __float_as_uint(Ps[(arow + 8) * BKS + kk]);
                uint32_t a2 = __float_as_uint(Ps[arow * BKS + kk + 4]);
                uint32_t a3 = __float_as_uint(Ps[(arow + 8) * BKS + kk + 4]);
                #pragma unroll
                for (int nf = 0; nf < 8; nf++) {
                    int col = wn * 64 + nf * 8 + gid;
                    uint32_t b0 = __float_as_uint(VTs[col * BKS + kk]);
                    uint32_t b1 = __float_as_uint(VTs[col * BKS + kk + 4]);
                    MMA_TF32(oacc[nf][0], oacc[nf][1], oacc[nf][2], oacc[nf][3],
                             a0, a1, a2, a3, b0, b1);
                }
            }
        }
    }

    {
        float li0 = 1.f / l_s[arow];
        float li1 = 1.f / l_s[arow + 8];
        const int row0 = q0 + arow;
        #pragma unroll
        for (int nf = 0; nf < 8; nf++) {
            int col = wn * 64 + nf * 8 + tig * 2;
            *(float2*)&g_o[(size_t)row0 * (N_HEADS * V_DIM) + h * V_DIM + col] =
                make_float2(to_tf32(oacc[nf][0] * li0), to_tf32(oacc[nf][1] * li0));
            *(float2*)&g_o[(size_t)(row0 + 8) * (N_HEADS * V_DIM) + h * V_DIM + col] =
                make_float2(to_tf32(oacc[nf][2] * li1), to_tf32(oacc[nf][3] * li1));
        }
    }
}

// ---------------------------------------------------------------------------
// Launcher
// ---------------------------------------------------------------------------
extern "C" void kernel_launch(void* const* d_in, const int* in_sizes, int n_in,
                              void* d_out, int out_size) {
    const float* x         = (const float*)d_in[0];
    const float* freqs     = (const float*)d_in[1];
    const float* wq_down   = (const float*)d_in[3];
    const float* q_norm_w  = (const float*)d_in[4];
    const float* wq_nope   = (const float*)d_in[5];
    const float* wq_rope   = (const float*)d_in[6];
    const float* wkv_down  = (const float*)d_in[7];
    const float* kv_norm_w = (const float*)d_in[8];
    const float* wkv_up    = (const float*)d_in[9];
    const float* wo        = (const float*)d_in[10];
    float* out = (float*)d_out;

    float *p_xr, *p_qdt, *p_qlat, *p_qnope, *p_qrope, *p_kvd, *p_ckvn, *p_kvup, *p_o;
    float *p_wqdT, *p_wqnT, *p_wqrT, *p_wkdT, *p_wkuT, *p_woT;
    cudaGetSymbolAddress((void**)&p_xr,    g_xr);
    cudaGetSymbolAddress((void**)&p_qdt,   g_qdt);
    cudaGetSymbolAddress((void**)&p_qlat,  g_qlat);
    cudaGetSymbolAddress((void**)&p_qnope, g_qnope);
    cudaGetSymbolAddress((void**)&p_qrope, g_qrope);
    cudaGetSymbolAddress((void**)&p_kvd,   g_kvd);
    cudaGetSymbolAddress((void**)&p_ckvn,  g_ckvn);
    cudaGetSymbolAddress((void**)&p_kvup,  g_kvup);
    cudaGetSymbolAddress((void**)&p_o,     g_o);
    cudaGetSymbolAddress((void**)&p_wqdT,  g_wqdT);
    cudaGetSymbolAddress((void**)&p_wqnT,  g_wqnT);
    cudaGetSymbolAddress((void**)&p_wqrT,  g_wqrT);
    cudaGetSymbolAddress((void**)&p_wkdT,  g_wkdT);
    cudaGetSymbolAddress((void**)&p_wkuT,  g_wkuT);
    cudaGetSymbolAddress((void**)&p_woT,   g_woT);

    cudaFuncSetAttribute(mma_gemm, cudaFuncAttributeMaxDynamicSharedMemorySize, GEMM_SMEM);
    cudaFuncSetAttribute(attn_mma, cudaFuncAttributeMaxDynamicSharedMemorySize, SMEM_ATTN2);

    const dim3 tb(32, 8);
    // round x; transpose+round weights
    round_tf32_kernel<<<(T_SEQ * DIM / 4 + 255) / 256, 256>>>(x, p_xr, T_SEQ * DIM / 4);
    transpose_tf32<<<dim3(Q_LORA / 32, DIM / 32), tb>>>(wq_down,  p_wqdT, DIM,    Q_LORA, Q_LORA);
    transpose_tf32<<<dim3((N_HEADS*NOPE) / 32, Q_LORA / 32), tb>>>(wq_nope, p_wqnT, Q_LORA, N_HEADS*NOPE, N_HEADS*NOPE);
    transpose_tf32<<<dim3((N_HEADS*ROPE) / 32, Q_LORA / 32), tb>>>(wq_rope, p_wqrT, Q_LORA, N_HEADS*ROPE, N_HEADS*ROPE);
    transpose_tf32<<<dim3(KVD_PAD / 32, DIM / 32), tb>>>(wkv_down, p_wkdT, DIM,   KV_LORA + ROPE, KVD_PAD);
    transpose_tf32<<<dim3((N_HEADS*(NOPE+V_DIM)) / 32, KV_LORA / 32), tb>>>(wkv_up, p_wkuT, KV_LORA, N_HEADS*(NOPE+V_DIM), N_HEADS*(NOPE+V_DIM));
    transpose_tf32<<<dim3(DIM / 32, (N_HEADS*V_DIM) / 32), tb>>>(wo, p_woT, N_HEADS*V_DIM, DIM, DIM);

    const int MB = T_SEQ / 128;   // 24

    mma_gemm<<<dim3(Q_LORA / 128, MB), 128, GEMM_SMEM>>>(p_xr, p_wqdT, p_qdt, T_SEQ, Q_LORA, DIM);
    rmsnorm_kernel<<<T_SEQ, 256>>>(p_qdt, q_norm_w, p_qlat, Q_LORA, Q_LORA, Q_LORA);
    mma_gemm<<<dim3((N_HEADS*NOPE) / 128, MB), 128, GEMM_SMEM>>>(p_qlat, p_wqnT, p_qnope, T_SEQ, N_HEADS*NOPE, Q_LORA);
    mma_gemm<<<dim3((N_HEADS*ROPE) / 128, MB), 128, GEMM_SMEM>>>(p_qlat, p_wqrT, p_qrope, T_SEQ, N_HEADS*ROPE, Q_LORA);
    mma_gemm<<<dim3(KVD_PAD / 128, MB), 128, GEMM_SMEM>>>(p_xr, p_wkdT, p_kvd, T_SEQ, KVD_PAD, DIM);
    rmsnorm_kernel<<<T_SEQ, 256>>>(p_kvd, kv_norm_w, p_ckvn, KVD_PAD, KV_LORA, KV_LORA);
    mma_gemm<<<dim3((N_HEADS*(NOPE+V_DIM)) / 128, MB), 128, GEMM_SMEM>>>(p_ckvn, p_wkuT, p_kvup, T_SEQ, N_HEADS*(NOPE+V_DIM), KV_LORA);
    assemble_q<<<T_SEQ, 256>>>(freqs);
    assemble_k<<<T_SEQ, 256>>>(freqs);
    attn_mma<<<dim3(T_SEQ / 64, N_HEADS), 256, SMEM_ATTN2>>>();
    mma_gemm<<<dim3(DIM / 128, MB), 128, GEMM_SMEM>>>(p_o, p_woT, out, T_SEQ, DIM, DIM);
}